// round 1
// baseline (speedup 1.0000x reference)
#include <cuda_runtime.h>

// Problem constants
#define NEG_INF_F (-1e10f)
static constexpr int BQ = 32, MQ = 64, CQ = 36;
static constexpr int HID = 512;

// Scratch (device globals: no allocation allowed)
__device__ float g_men_h[2048 * 512];
__device__ float g_men  [2048 * 512];
__device__ float g_vis_h[1152 * 512];
__device__ float g_vis  [1152 * 512];

// ---------------------------------------------------------------------------
// Generic tiled SGEMM: C[rows][512] = act(A[rows][K] @ W[K][512] + bias)
// rows % 128 == 0, N = 512 fixed, K arbitrary (zero-fill guard).
// grid: (512/128, rows/128), 256 threads. 128x128 tile, 8x8 per thread,
// split-column mapping (tx*4 and 64+tx*4) for conflict-free float4 SMEM reads.
// ---------------------------------------------------------------------------
template <bool RELU>
__global__ __launch_bounds__(256)
void gemm512(const float* __restrict__ A, const float* __restrict__ W,
             const float* __restrict__ bias, float* __restrict__ C, int K)
{
    __shared__ __align__(16) float A_s[16][132];
    __shared__ __align__(16) float B_s[16][132];

    const int tid = threadIdx.x;
    const int tx = tid & 15, ty = tid >> 4;
    const int row0 = blockIdx.y * 128;
    const int n0   = blockIdx.x * 128;

    float acc[8][8];
#pragma unroll
    for (int i = 0; i < 8; i++)
#pragma unroll
        for (int j = 0; j < 8; j++) acc[i][j] = 0.f;

    for (int k0 = 0; k0 < K; k0 += 16) {
        __syncthreads();
        // A tile: 128 rows x 16 k (scalar loads, 64B-coalesced per 16 threads)
#pragma unroll
        for (int p = 0; p < 8; p++) {
            int id = tid + p * 256;
            int r = id >> 4, kk = id & 15;
            float v = 0.f;
            if (k0 + kk < K) v = A[(size_t)(row0 + r) * K + k0 + kk];
            A_s[kk][r] = v;
        }
        // B tile: 16 k x 128 n (float4, fully coalesced)
#pragma unroll
        for (int p = 0; p < 2; p++) {
            int id = tid + p * 256;
            int kk = id >> 5, nn = id & 31;
            float4 v = make_float4(0.f, 0.f, 0.f, 0.f);
            if (k0 + kk < K)
                v = *(const float4*)&W[(size_t)(k0 + kk) * 512 + n0 + nn * 4];
            *(float4*)&B_s[kk][nn * 4] = v;
        }
        __syncthreads();

#pragma unroll
        for (int kk = 0; kk < 16; kk++) {
            float4 a0 = *(float4*)&A_s[kk][ty * 4];
            float4 a1 = *(float4*)&A_s[kk][64 + ty * 4];
            float4 b0 = *(float4*)&B_s[kk][tx * 4];
            float4 b1 = *(float4*)&B_s[kk][64 + tx * 4];
            float av[8] = {a0.x, a0.y, a0.z, a0.w, a1.x, a1.y, a1.z, a1.w};
            float bv[8] = {b0.x, b0.y, b0.z, b0.w, b1.x, b1.y, b1.z, b1.w};
#pragma unroll
            for (int i = 0; i < 8; i++)
#pragma unroll
                for (int j = 0; j < 8; j++) acc[i][j] += av[i] * bv[j];
        }
    }

    // Epilogue: bias (+relu), float4 stores
    float4 bb0 = *(const float4*)&bias[n0 + tx * 4];
    float4 bb1 = *(const float4*)&bias[n0 + 64 + tx * 4];
    float bbv[8] = {bb0.x, bb0.y, bb0.z, bb0.w, bb1.x, bb1.y, bb1.z, bb1.w};
#pragma unroll
    for (int i = 0; i < 8; i++) {
        int row = row0 + ((i < 4) ? (ty * 4 + i) : (64 + ty * 4 + i - 4));
        float o[8];
#pragma unroll
        for (int j = 0; j < 8; j++) {
            float v = acc[i][j] + bbv[j];
            if (RELU) v = fmaxf(v, 0.f);
            o[j] = v;
        }
        *(float4*)&C[(size_t)row * 512 + n0 + tx * 4]      = make_float4(o[0], o[1], o[2], o[3]);
        *(float4*)&C[(size_t)row * 512 + n0 + 64 + tx * 4] = make_float4(o[4], o[5], o[6], o[7]);
    }
}

// ---------------------------------------------------------------------------
// Fused attention kernel.
// attn[b,m,c] = relu((men[b,m] * vis[b,c]) @ aw1 + ab1) @ aw2 + ab2, then mask.
// Block = (b, 32 m-rows, 4 c-cols) -> 128 "prod" rows, never materialized:
// a[row][k] = men_s[k][lm] * vis_s[k][lc]. K=512 loop, N=512 looped in 4
// tiles of 128 inside the block, relu+aw2 dot accumulated in registers,
// cross-thread reduce via shfl, single masked store per output.
// grid: (9, 2, 32), 256 threads.
// ---------------------------------------------------------------------------
__global__ __launch_bounds__(256)
void attn_kernel(const float* __restrict__ men, const float* __restrict__ vis,
                 const float* __restrict__ aw1, const float* __restrict__ ab1,
                 const float* __restrict__ aw2, const float* __restrict__ ab2,
                 const float* __restrict__ mm,  const float* __restrict__ cm,
                 float* __restrict__ out)
{
    __shared__ __align__(16) float men_s[16][33];
    __shared__ __align__(16) float vis_s[16][4];
    __shared__ __align__(16) float b_s[16][132];

    const int tid = threadIdx.x;
    const int tx = tid & 15, ty = tid >> 4;
    const int c0 = blockIdx.x * 4;
    const int m0 = blockIdx.y * 32;
    const int b  = blockIdx.z;

    const float* menB = men + ((size_t)b * MQ + m0) * HID;
    const float* visB = vis + ((size_t)b * CQ + c0) * HID;

    float attn_acc[8] = {0.f, 0.f, 0.f, 0.f, 0.f, 0.f, 0.f, 0.f};

    for (int nt = 0; nt < 4; nt++) {
        const int n0 = nt * 128;
        float acc[8][8];
#pragma unroll
        for (int i = 0; i < 8; i++)
#pragma unroll
            for (int j = 0; j < 8; j++) acc[i][j] = 0.f;

        for (int k0 = 0; k0 < HID; k0 += 16) {
            __syncthreads();
            // men tile: 32 rows x 16 k
#pragma unroll
            for (int p = 0; p < 2; p++) {
                int id = tid + p * 256;
                int lm = id >> 4, kk = id & 15;
                men_s[kk][lm] = menB[(size_t)lm * HID + k0 + kk];
            }
            // vis tile: 4 rows x 16 k
            if (tid < 64) {
                int lc = tid >> 4, kk = tid & 15;
                vis_s[kk][lc] = visB[(size_t)lc * HID + k0 + kk];
            }
            // aw1 tile: 16 k x 128 n
#pragma unroll
            for (int p = 0; p < 2; p++) {
                int id = tid + p * 256;
                int kk = id >> 5, nn = id & 31;
                *(float4*)&b_s[kk][nn * 4] =
                    *(const float4*)&aw1[(size_t)(k0 + kk) * 512 + n0 + nn * 4];
            }
            __syncthreads();

#pragma unroll
            for (int kk = 0; kk < 16; kk++) {
                float mv0 = men_s[kk][ty];
                float mv1 = men_s[kk][16 + ty];
                float4 vv = *(float4*)&vis_s[kk][0];
                float av[8] = {mv0 * vv.x, mv0 * vv.y, mv0 * vv.z, mv0 * vv.w,
                               mv1 * vv.x, mv1 * vv.y, mv1 * vv.z, mv1 * vv.w};
                float4 b0 = *(float4*)&b_s[kk][tx * 4];
                float4 b1 = *(float4*)&b_s[kk][64 + tx * 4];
                float bv[8] = {b0.x, b0.y, b0.z, b0.w, b1.x, b1.y, b1.z, b1.w};
#pragma unroll
                for (int i = 0; i < 8; i++)
#pragma unroll
                    for (int j = 0; j < 8; j++) acc[i][j] += av[i] * bv[j];
            }
        }

        // n-tile epilogue: h = relu(acc + ab1); attn += h * aw2
#pragma unroll
        for (int j = 0; j < 8; j++) {
            int n = n0 + ((j < 4) ? (tx * 4 + j) : (64 + tx * 4 + j - 4));
            float bb = ab1[n];
            float w2 = aw2[n];
#pragma unroll
            for (int i = 0; i < 8; i++) {
                float h = fmaxf(acc[i][j] + bb, 0.f);
                attn_acc[i] += h * w2;
            }
        }
    }

    // Reduce over the 16 tx lanes sharing each row, mask, store.
    float bias2 = ab2[0];
#pragma unroll
    for (int i = 0; i < 8; i++) {
        float v = attn_acc[i];
        v += __shfl_xor_sync(0xffffffffu, v, 8);
        v += __shfl_xor_sync(0xffffffffu, v, 4);
        v += __shfl_xor_sync(0xffffffffu, v, 2);
        v += __shfl_xor_sync(0xffffffffu, v, 1);
        if (tx == 0) {
            int lm = (i < 4) ? ty : (16 + ty);
            int lc = (i < 4) ? i : (i - 4);
            int m = m0 + lm, c = c0 + lc;
            float val = v + bias2;
            val *= mm[b * MQ + m] * cm[b * CQ + c];
            out[((size_t)b * MQ + m) * CQ + c] = (val != 0.f) ? val : NEG_INF_F;
        }
    }
}

extern "C" void kernel_launch(void* const* d_in, const int* in_sizes, int n_in,
                              void* d_out, int out_size)
{
    const float* me  = (const float*)d_in[0];   // (32,64,1024)
    const float* cl  = (const float*)d_in[1];   // (32,36,1000)
    const float* mm  = (const float*)d_in[2];   // (32,64)
    const float* cm  = (const float*)d_in[3];   // (32,36)
    const float* vw1 = (const float*)d_in[4];
    const float* vb1 = (const float*)d_in[5];
    const float* vw2 = (const float*)d_in[6];
    const float* vb2 = (const float*)d_in[7];
    const float* mw1 = (const float*)d_in[8];
    const float* mb1 = (const float*)d_in[9];
    const float* mw2 = (const float*)d_in[10];
    const float* mb2 = (const float*)d_in[11];
    const float* aw1 = (const float*)d_in[12];
    const float* ab1 = (const float*)d_in[13];
    const float* aw2 = (const float*)d_in[14];
    const float* ab2 = (const float*)d_in[15];
    float* out = (float*)d_out;

    void *p_men_h, *p_men, *p_vis_h, *p_vis;
    cudaGetSymbolAddress(&p_men_h, g_men_h);
    cudaGetSymbolAddress(&p_men,   g_men);
    cudaGetSymbolAddress(&p_vis_h, g_vis_h);
    cudaGetSymbolAddress(&p_vis,   g_vis);
    float* men_h = (float*)p_men_h;
    float* menp  = (float*)p_men;
    float* vis_h = (float*)p_vis_h;
    float* visp  = (float*)p_vis;

    // mention MLP: 2048 rows
    gemm512<true ><<<dim3(4, 16), 256>>>(me,    mw1, mb1, men_h, 1024);
    gemm512<false><<<dim3(4, 16), 256>>>(men_h, mw2, mb2, menp,  512);
    // visual MLP: 1152 rows
    gemm512<true ><<<dim3(4, 9),  256>>>(cl,    vw1, vb1, vis_h, 1000);
    gemm512<false><<<dim3(4, 9),  256>>>(vis_h, vw2, vb2, visp,  512);
    // fused attention
    attn_kernel<<<dim3(9, 2, 32), 256>>>(menp, visp, aw1, ab1, aw2, ab2,
                                         mm, cm, out);
}

// round 3
// speedup vs baseline: 6.3130x; 6.3130x over previous
#include <cuda_runtime.h>

#define NEG_INF_F (-1e10f)
// Shapes: B=32, M=64, C=36, INPUT=1024, HID=512, NCLASS=1000 (padded to 1024)

// ---------------- scratch (device globals; no allocation allowed) ----------
__device__ float    g_men_h[2048 * 512];
__device__ float    g_men  [2048 * 512];
__device__ float    g_vis_h[1152 * 512];
__device__ float    g_vis  [1152 * 512];
__device__ float    g_cl_pad[1152 * 1024];
__device__ unsigned g_mw1t[1024 * 512];
__device__ unsigned g_mw2t[ 512 * 512];
__device__ unsigned g_vw1t[1024 * 512];
__device__ unsigned g_vw2t[ 512 * 512];
__device__ unsigned g_aw1t[ 512 * 512];

// ---------------- PTX helpers ---------------------------------------------
__device__ __forceinline__ unsigned f2tf32(float x) {
    unsigned u;
    asm("cvt.rna.tf32.f32 %0, %1;" : "=r"(u) : "f"(x));
    return u;
}

__device__ __forceinline__ void mma_tf32(float c[4],
                                         unsigned a0, unsigned a1, unsigned a2, unsigned a3,
                                         unsigned b0, unsigned b1) {
    asm volatile(
        "mma.sync.aligned.m16n8k8.row.col.f32.tf32.tf32.f32 "
        "{%0,%1,%2,%3}, {%4,%5,%6,%7}, {%8,%9}, {%0,%1,%2,%3};\n"
        : "+f"(c[0]), "+f"(c[1]), "+f"(c[2]), "+f"(c[3])
        : "r"(a0), "r"(a1), "r"(a2), "r"(a3), "r"(b0), "r"(b1));
}

__device__ __forceinline__ void cp16(void* smem, const void* gmem) {
    unsigned s = (unsigned)__cvta_generic_to_shared(smem);
    asm volatile("cp.async.cg.shared.global [%0], [%1], 16;\n" :: "r"(s), "l"(gmem));
}
#define CP_COMMIT() asm volatile("cp.async.commit_group;\n" ::: "memory")
#define CP_WAIT0()  asm volatile("cp.async.wait_group 0;\n" ::: "memory")
#define CP_WAIT1()  asm volatile("cp.async.wait_group 1;\n" ::: "memory")

// ---------------- prep kernels --------------------------------------------
// class_labels (1152 x 1000) -> zero-padded (1152 x 1024)
__global__ void pad_cl_kernel(const float* __restrict__ src, float* __restrict__ dst) {
    int row = blockIdx.x;
    for (int c = threadIdx.x; c < 1024; c += blockDim.x)
        dst[row * 1024 + c] = (c < 1000) ? src[row * 1000 + c] : 0.f;
}

// weight f32 (src_rows x 512) -> tf32 bits, zero-padded above src_rows
__global__ void cvt_w_kernel(const float* __restrict__ src, unsigned* __restrict__ dst,
                             int src_rows) {
    int row = blockIdx.x;
    bool valid = row < src_rows;
    for (int c = threadIdx.x; c < 512; c += blockDim.x)
        dst[row * 512 + c] = valid ? f2tf32(src[row * 512 + c]) : 0u;
}

// ---------------- MLP GEMM: C[rows x 512] = act(A[rows x K] @ W + bias) ----
// W pre-converted to tf32 bits. rows%64==0, K%32==0. Block 64x64, 8 warps
// (4 row-groups x 2 col-groups), warp tile 16x32, mma m16n8k8 tf32.
template <bool RELU>
__global__ __launch_bounds__(256)
void gemm_mma(const float* __restrict__ A, const unsigned* __restrict__ W,
              const float* __restrict__ bias, float* __restrict__ C, int K)
{
    __shared__ __align__(16) float    A_s[2][64][36];
    __shared__ __align__(16) unsigned B_s[2][32][72];   // 64 cols + 8 pad (was 40: OOB bug)

    const int tid = threadIdx.x;
    const int lane = tid & 31, wid = tid >> 5;
    const int wr = wid >> 1;        // warp row-group (0..3) -> 16 rows
    const int wcl = wid & 1;        // warp col-group (0..1) -> 32 cols
    const int row0 = blockIdx.y * 64;
    const int n0   = blockIdx.x * 64;

    float acc[4][4];
#pragma unroll
    for (int t = 0; t < 4; t++)
#pragma unroll
        for (int j = 0; j < 4; j++) acc[t][j] = 0.f;

    const int S = K >> 5;

    // stage issue: A 64x32 (512 x 16B), B 32x64 (512 x 16B)
    auto issue = [&](int s) {
        int buf = s & 1, k0 = s << 5;
#pragma unroll
        for (int p = 0; p < 2; p++) {
            int id = tid + p * 256;
            int r = id >> 3, k4 = id & 7;
            cp16(&A_s[buf][r][k4 * 4], A + (size_t)(row0 + r) * K + k0 + k4 * 4);
        }
#pragma unroll
        for (int p = 0; p < 2; p++) {
            int id = tid + p * 256;
            int kk = id >> 4, n4 = id & 15;
            cp16(&B_s[buf][kk][n4 * 4], W + (size_t)(k0 + kk) * 512 + n0 + n4 * 4);
        }
    };

    issue(0);
    CP_COMMIT();

    for (int s = 0; s < S; s++) {
        if (s + 1 < S) { issue(s + 1); CP_COMMIT(); CP_WAIT1(); }
        else           { CP_WAIT0(); }
        __syncthreads();
        const int buf = s & 1;
#pragma unroll
        for (int kc = 0; kc < 4; kc++) {
            const int k0 = kc * 8;
            const int ar = wr * 16 + (lane >> 2);
            const int ak = k0 + (lane & 3);
            unsigned a0 = f2tf32(A_s[buf][ar][ak]);
            unsigned a1 = f2tf32(A_s[buf][ar + 8][ak]);
            unsigned a2 = f2tf32(A_s[buf][ar][ak + 4]);
            unsigned a3 = f2tf32(A_s[buf][ar + 8][ak + 4]);
            const int bn = wcl * 32 + (lane >> 2);
#pragma unroll
            for (int t = 0; t < 4; t++) {
                unsigned b0 = B_s[buf][k0 + (lane & 3)][bn + t * 8];
                unsigned b1 = B_s[buf][k0 + (lane & 3) + 4][bn + t * 8];
                mma_tf32(acc[t], a0, a1, a2, a3, b0, b1);
            }
        }
        __syncthreads();
    }

    // epilogue: C frag rows lane/4 (+8); cols 2*(lane%4) (+1)
    const int r = row0 + wr * 16 + (lane >> 2);
#pragma unroll
    for (int t = 0; t < 4; t++) {
        int n = n0 + wcl * 32 + t * 8 + 2 * (lane & 3);
        float b0v = __ldg(&bias[n]), b1v = __ldg(&bias[n + 1]);
        float v00 = acc[t][0] + b0v, v01 = acc[t][1] + b1v;
        float v10 = acc[t][2] + b0v, v11 = acc[t][3] + b1v;
        if (RELU) {
            v00 = fmaxf(v00, 0.f); v01 = fmaxf(v01, 0.f);
            v10 = fmaxf(v10, 0.f); v11 = fmaxf(v11, 0.f);
        }
        C[(size_t)r * 512 + n]           = v00;
        C[(size_t)r * 512 + n + 1]       = v01;
        C[(size_t)(r + 8) * 512 + n]     = v10;
        C[(size_t)(r + 8) * 512 + n + 1] = v11;
    }
}

// ---------------- fused attention (tf32 mma) -------------------------------
// attn[b,m,c] = relu((men[b,m]*vis[b,c]) @ aw1 + ab1) @ aw2 + ab2, masked.
// Block: b fixed, 32 m-rows x 4 c -> 128 prod rows, built in registers per
// fragment (a = cvt.tf32(men*vis)). 8 warps = 4 c x 2 n-halves; warp tile
// 32 rows x 64 cols. N looped in 4x128, K in 16 double-buffered stages of 32.
__global__ __launch_bounds__(256)
void attn_mma(const float* __restrict__ men, const float* __restrict__ vis,
              const unsigned* __restrict__ aw1t,
              const float* __restrict__ ab1, const float* __restrict__ aw2,
              const float* __restrict__ ab2,
              const float* __restrict__ mm, const float* __restrict__ cm,
              float* __restrict__ out)
{
    __shared__ __align__(16) float    men_s[2][32][36];
    __shared__ __align__(16) float    vis_s[2][4][36];
    __shared__ __align__(16) unsigned b_s[2][32][136];
    __shared__ float attn_s[2][4][32];

    const int tid = threadIdx.x;
    const int lane = tid & 31, wid = tid >> 5;
    const int wc = wid >> 1;        // warp's class index within tile (0..3)
    const int wn = wid & 1;         // warp n-half (0..1) -> 64 cols
    const int c0 = blockIdx.x * 4;
    const int m0 = blockIdx.y * 32;
    const int b  = blockIdx.z;

    const float* menB = men + (size_t)(b * 64 + m0) * 512;
    const float* visB = vis + (size_t)(b * 36 + c0) * 512;

    float acc0[8][4], acc1[8][4];
    float attn_acc[4] = {0.f, 0.f, 0.f, 0.f};

    auto issue = [&](int s) {
        int buf = s & 1;
        int k0 = (s & 15) * 32, n0 = (s >> 4) * 128;
        {   // men: 32 rows x 32 k = 256 x 16B chunks
            int r = tid >> 3, k4 = tid & 7;
            cp16(&men_s[buf][r][k4 * 4], menB + (size_t)r * 512 + k0 + k4 * 4);
        }
        if (tid < 32) {  // vis: 4 x 32
            int c = tid >> 3, k4 = tid & 7;
            cp16(&vis_s[buf][c][k4 * 4], visB + (size_t)c * 512 + k0 + k4 * 4);
        }
#pragma unroll
        for (int p = 0; p < 4; p++) {  // aw1 tile: 32k x 128n = 1024 chunks
            int id = tid + p * 256;
            int kk = id >> 5, n4 = id & 31;
            cp16(&b_s[buf][kk][n4 * 4], aw1t + (size_t)(k0 + kk) * 512 + n0 + n4 * 4);
        }
    };

    issue(0);
    CP_COMMIT();

    for (int s = 0; s < 64; s++) {
        if (s + 1 < 64) { issue(s + 1); CP_COMMIT(); CP_WAIT1(); }
        else            { CP_WAIT0(); }
        __syncthreads();

        const int buf = s & 1;
        const int ks = s & 15, ni = s >> 4;

        if (ks == 0) {
#pragma unroll
            for (int t = 0; t < 8; t++)
#pragma unroll
                for (int j = 0; j < 4; j++) { acc0[t][j] = 0.f; acc1[t][j] = 0.f; }
        }

#pragma unroll
        for (int kc = 0; kc < 4; kc++) {
            const int k0 = kc * 8;
            const int kA = k0 + (lane & 3);
            const int mr = lane >> 2;
            // vis broadcast (warp-uniform c)
            float v0 = vis_s[buf][wc][kA];
            float v1 = vis_s[buf][wc][kA + 4];
            // men rows: mr, mr+8 (tile0), mr+16, mr+24 (tile1)
            float m00 = men_s[buf][mr][kA],      m01 = men_s[buf][mr][kA + 4];
            float m10 = men_s[buf][mr + 8][kA],  m11 = men_s[buf][mr + 8][kA + 4];
            float m20 = men_s[buf][mr + 16][kA], m21 = men_s[buf][mr + 16][kA + 4];
            float m30 = men_s[buf][mr + 24][kA], m31 = men_s[buf][mr + 24][kA + 4];
            unsigned a00 = f2tf32(m00 * v0), a01 = f2tf32(m10 * v0);
            unsigned a02 = f2tf32(m01 * v1), a03 = f2tf32(m11 * v1);
            unsigned a10 = f2tf32(m20 * v0), a11 = f2tf32(m30 * v0);
            unsigned a12 = f2tf32(m21 * v1), a13 = f2tf32(m31 * v1);
            const int bn = wn * 64 + (lane >> 2);
#pragma unroll
            for (int t = 0; t < 8; t++) {
                unsigned b0 = b_s[buf][k0 + (lane & 3)][bn + t * 8];
                unsigned b1 = b_s[buf][k0 + (lane & 3) + 4][bn + t * 8];
                mma_tf32(acc0[t], a00, a01, a02, a03, b0, b1);
                mma_tf32(acc1[t], a10, a11, a12, a13, b0, b1);
            }
        }

        if (ks == 15) {
            // fold this N-range: attn += relu(acc + ab1[n]) * aw2[n]
            const int nbase = ni * 128 + wn * 64;
#pragma unroll
            for (int t = 0; t < 8; t++) {
                int n = nbase + t * 8 + 2 * (lane & 3);
                float bb0 = __ldg(&ab1[n]),     bb1 = __ldg(&ab1[n + 1]);
                float w0  = __ldg(&aw2[n]),     w1  = __ldg(&aw2[n + 1]);
                attn_acc[0] += fmaxf(acc0[t][0] + bb0, 0.f) * w0
                             + fmaxf(acc0[t][1] + bb1, 0.f) * w1;
                attn_acc[1] += fmaxf(acc0[t][2] + bb0, 0.f) * w0
                             + fmaxf(acc0[t][3] + bb1, 0.f) * w1;
                attn_acc[2] += fmaxf(acc1[t][0] + bb0, 0.f) * w0
                             + fmaxf(acc1[t][1] + bb1, 0.f) * w1;
                attn_acc[3] += fmaxf(acc1[t][2] + bb0, 0.f) * w0
                             + fmaxf(acc1[t][3] + bb1, 0.f) * w1;
            }
        }
        __syncthreads();
    }

    // reduce the 4 col-pair lanes (lane%4), stash per n-half partials
#pragma unroll
    for (int i = 0; i < 4; i++) {
        float v = attn_acc[i];
        v += __shfl_xor_sync(0xffffffffu, v, 1);
        v += __shfl_xor_sync(0xffffffffu, v, 2);
        if ((lane & 3) == 0) attn_s[wn][wc][i * 8 + (lane >> 2)] = v;
    }
    __syncthreads();

    if (tid < 128) {
        int m = tid & 31, c = tid >> 5;
        float v = attn_s[0][c][m] + attn_s[1][c][m] + ab2[0];
        int gm = m0 + m, gc = c0 + c;
        v *= mm[b * 64 + gm] * cm[b * 36 + gc];
        out[(size_t)(b * 64 + gm) * 36 + gc] = (v != 0.f) ? v : NEG_INF_F;
    }
}

// ---------------- launch ---------------------------------------------------
extern "C" void kernel_launch(void* const* d_in, const int* in_sizes, int n_in,
                              void* d_out, int out_size)
{
    const float* me  = (const float*)d_in[0];   // (32,64,1024)
    const float* cl  = (const float*)d_in[1];   // (32,36,1000)
    const float* mm  = (const float*)d_in[2];   // (32,64)
    const float* cm  = (const float*)d_in[3];   // (32,36)
    const float* vw1 = (const float*)d_in[4];   // (1000,512)
    const float* vb1 = (const float*)d_in[5];
    const float* vw2 = (const float*)d_in[6];   // (512,512)
    const float* vb2 = (const float*)d_in[7];
    const float* mw1 = (const float*)d_in[8];   // (1024,512)
    const float* mb1 = (const float*)d_in[9];
    const float* mw2 = (const float*)d_in[10];  // (512,512)
    const float* mb2 = (const float*)d_in[11];
    const float* aw1 = (const float*)d_in[12];  // (512,512)
    const float* ab1 = (const float*)d_in[13];
    const float* aw2 = (const float*)d_in[14];  // (512,1)
    const float* ab2 = (const float*)d_in[15];
    float* out = (float*)d_out;

    void *p;
    cudaGetSymbolAddress(&p, g_men_h);  float*    men_h = (float*)p;
    cudaGetSymbolAddress(&p, g_men);    float*    menp  = (float*)p;
    cudaGetSymbolAddress(&p, g_vis_h);  float*    vis_h = (float*)p;
    cudaGetSymbolAddress(&p, g_vis);    float*    visp  = (float*)p;
    cudaGetSymbolAddress(&p, g_cl_pad); float*    clp   = (float*)p;
    cudaGetSymbolAddress(&p, g_mw1t);   unsigned* mw1t  = (unsigned*)p;
    cudaGetSymbolAddress(&p, g_mw2t);   unsigned* mw2t  = (unsigned*)p;
    cudaGetSymbolAddress(&p, g_vw1t);   unsigned* vw1t  = (unsigned*)p;
    cudaGetSymbolAddress(&p, g_vw2t);   unsigned* vw2t  = (unsigned*)p;
    cudaGetSymbolAddress(&p, g_aw1t);   unsigned* aw1t  = (unsigned*)p;

    // prep
    pad_cl_kernel<<<1152, 256>>>(cl, clp);
    cvt_w_kernel<<<1024, 256>>>(mw1, mw1t, 1024);
    cvt_w_kernel<<< 512, 256>>>(mw2, mw2t,  512);
    cvt_w_kernel<<<1024, 256>>>(vw1, vw1t, 1000);  // zero-pad rows 1000..1023
    cvt_w_kernel<<< 512, 256>>>(vw2, vw2t,  512);
    cvt_w_kernel<<< 512, 256>>>(aw1, aw1t,  512);

    // MLPs (tf32 tensor cores)
    gemm_mma<true ><<<dim3(8, 32), 256>>>(me,    mw1t, mb1, men_h, 1024);
    gemm_mma<false><<<dim3(8, 32), 256>>>(men_h, mw2t, mb2, menp,   512);
    gemm_mma<true ><<<dim3(8, 18), 256>>>(clp,   vw1t, vb1, vis_h, 1024);
    gemm_mma<false><<<dim3(8, 18), 256>>>(vis_h, vw2t, vb2, visp,   512);

    // fused attention
    attn_mma<<<dim3(9, 2, 32), 256>>>(menp, visp, aw1t, ab1, aw2, ab2,
                                      mm, cm, out);
}

// round 4
// speedup vs baseline: 7.3939x; 1.1712x over previous
#include <cuda_runtime.h>

#define NEG_INF_F (-1e10f)
// Shapes: B=32, M=64, C=36, INPUT=1024, HID=512, NCLASS=1000 (padded to 1024)

// ---------------- scratch (device globals; no allocation allowed) ----------
__device__ float    g_men_h[2048 * 512];
__device__ float    g_men  [2048 * 512];
__device__ float    g_vis_h[1152 * 512];
__device__ float    g_vis  [1152 * 512];
__device__ float    g_cl_pad[1152 * 1024];
__device__ unsigned g_mw1t[1024 * 512];
__device__ unsigned g_mw2t[ 512 * 512];
__device__ unsigned g_vw1t[1024 * 512];
__device__ unsigned g_vw2t[ 512 * 512];
// aw1 packed in mma-fragment order: 512 chunks x 576 words (incl. skew holes)
__device__ __align__(16) unsigned g_aw1p[512 * 576];

// ---------------- PTX helpers ---------------------------------------------
__device__ __forceinline__ unsigned f2tf32(float x) {
    unsigned u;
    asm("cvt.rna.tf32.f32 %0, %1;" : "=r"(u) : "f"(x));
    return u;
}

__device__ __forceinline__ void mma_tf32(float c[4],
                                         unsigned a0, unsigned a1, unsigned a2, unsigned a3,
                                         unsigned b0, unsigned b1) {
    asm volatile(
        "mma.sync.aligned.m16n8k8.row.col.f32.tf32.tf32.f32 "
        "{%0,%1,%2,%3}, {%4,%5,%6,%7}, {%8,%9}, {%0,%1,%2,%3};\n"
        : "+f"(c[0]), "+f"(c[1]), "+f"(c[2]), "+f"(c[3])
        : "r"(a0), "r"(a1), "r"(a2), "r"(a3), "r"(b0), "r"(b1));
}

__device__ __forceinline__ void cp16(void* smem, const void* gmem) {
    unsigned s = (unsigned)__cvta_generic_to_shared(smem);
    asm volatile("cp.async.cg.shared.global [%0], [%1], 16;\n" :: "r"(s), "l"(gmem));
}
#define CP_COMMIT() asm volatile("cp.async.commit_group;\n" ::: "memory")
#define CP_WAIT0()  asm volatile("cp.async.wait_group 0;\n" ::: "memory")
#define CP_WAIT1()  asm volatile("cp.async.wait_group 1;\n" ::: "memory")

// ---------------- single merged prep kernel --------------------------------
// Segmented by blockIdx.x:
//  [0,1152)     pad class_labels 1000 -> 1024
//  [1152,2176)  cvt mw1 (1024 rows)
//  [2176,2688)  cvt mw2 (512)
//  [2688,3712)  cvt vw1 (1000 rows, zero-pad to 1024)
//  [3712,4224)  cvt vw2 (512)
//  [4224,4736)  pack aw1 into fragment-order chunks
__global__ __launch_bounds__(256)
void prep_all(const float* __restrict__ cl,  float* __restrict__ clp,
              const float* __restrict__ mw1, unsigned* __restrict__ mw1t,
              const float* __restrict__ mw2, unsigned* __restrict__ mw2t,
              const float* __restrict__ vw1, unsigned* __restrict__ vw1t,
              const float* __restrict__ vw2, unsigned* __restrict__ vw2t,
              const float* __restrict__ aw1, unsigned* __restrict__ awp)
{
    const int b = blockIdx.x, t = threadIdx.x;
    if (b < 1152) {
        for (int c = t; c < 1024; c += 256)
            clp[b * 1024 + c] = (c < 1000) ? cl[b * 1000 + c] : 0.f;
    } else if (b < 2176) {
        int r = b - 1152;
        for (int c = t; c < 512; c += 256) mw1t[r * 512 + c] = f2tf32(mw1[r * 512 + c]);
    } else if (b < 2688) {
        int r = b - 2176;
        for (int c = t; c < 512; c += 256) mw2t[r * 512 + c] = f2tf32(mw2[r * 512 + c]);
    } else if (b < 3712) {
        int r = b - 2688;
        for (int c = t; c < 512; c += 256)
            vw1t[r * 512 + c] = (r < 1000) ? f2tf32(vw1[r * 512 + c]) : 0u;
    } else if (b < 4224) {
        int r = b - 3712;
        for (int c = t; c < 512; c += 256) vw2t[r * 512 + c] = f2tf32(vw2[r * 512 + c]);
    } else {
        // pack aw1: chunk = ((ni*16 + ksi)*4 + kc)*2 + h covers 8k x 64n.
        // Value (l, v): k = ksi*32+kc*8+(l&3)+4*(v&1), n = ni*128+h*64+(v>>1)*8+(l>>2).
        // In-chunk word offset = l*16 + (l>>1)*4 + v  (lane skew -> conflict-free LDS.128)
        int chunk = b - 4224;
        int h   = chunk & 1;
        int kc  = (chunk >> 1) & 3;
        int ksi = (chunk >> 3) & 15;
        int ni  = chunk >> 7;
#pragma unroll
        for (int p = 0; p < 2; p++) {
            int idx = t + p * 256;          // 512 values per chunk
            int l = idx >> 4, v = idx & 15;
            int k = ksi * 32 + kc * 8 + (l & 3) + 4 * (v & 1);
            int n = ni * 128 + h * 64 + (v >> 1) * 8 + (l >> 2);
            awp[chunk * 576 + l * 16 + (l >> 1) * 4 + v] = f2tf32(aw1[k * 512 + n]);
        }
    }
}

// ---------------- MLP GEMM: C[rows x 512] = act(A[rows x K] @ W + bias) ----
// (unchanged from round 3 — proven correct)
template <bool RELU>
__global__ __launch_bounds__(256)
void gemm_mma(const float* __restrict__ A, const unsigned* __restrict__ W,
              const float* __restrict__ bias, float* __restrict__ C, int K)
{
    __shared__ __align__(16) float    A_s[2][64][36];
    __shared__ __align__(16) unsigned B_s[2][32][72];

    const int tid = threadIdx.x;
    const int lane = tid & 31, wid = tid >> 5;
    const int wr = wid >> 1;
    const int wcl = wid & 1;
    const int row0 = blockIdx.y * 64;
    const int n0   = blockIdx.x * 64;

    float acc[4][4];
#pragma unroll
    for (int t = 0; t < 4; t++)
#pragma unroll
        for (int j = 0; j < 4; j++) acc[t][j] = 0.f;

    const int S = K >> 5;

    auto issue = [&](int s) {
        int buf = s & 1, k0 = s << 5;
#pragma unroll
        for (int p = 0; p < 2; p++) {
            int id = tid + p * 256;
            int r = id >> 3, k4 = id & 7;
            cp16(&A_s[buf][r][k4 * 4], A + (size_t)(row0 + r) * K + k0 + k4 * 4);
        }
#pragma unroll
        for (int p = 0; p < 2; p++) {
            int id = tid + p * 256;
            int kk = id >> 4, n4 = id & 15;
            cp16(&B_s[buf][kk][n4 * 4], W + (size_t)(k0 + kk) * 512 + n0 + n4 * 4);
        }
    };

    issue(0);
    CP_COMMIT();

    for (int s = 0; s < S; s++) {
        if (s + 1 < S) { issue(s + 1); CP_COMMIT(); CP_WAIT1(); }
        else           { CP_WAIT0(); }
        __syncthreads();
        const int buf = s & 1;
#pragma unroll
        for (int kc = 0; kc < 4; kc++) {
            const int k0 = kc * 8;
            const int ar = wr * 16 + (lane >> 2);
            const int ak = k0 + (lane & 3);
            unsigned a0 = f2tf32(A_s[buf][ar][ak]);
            unsigned a1 = f2tf32(A_s[buf][ar + 8][ak]);
            unsigned a2 = f2tf32(A_s[buf][ar][ak + 4]);
            unsigned a3 = f2tf32(A_s[buf][ar + 8][ak + 4]);
            const int bn = wcl * 32 + (lane >> 2);
#pragma unroll
            for (int t = 0; t < 4; t++) {
                unsigned b0 = B_s[buf][k0 + (lane & 3)][bn + t * 8];
                unsigned b1 = B_s[buf][k0 + (lane & 3) + 4][bn + t * 8];
                mma_tf32(acc[t], a0, a1, a2, a3, b0, b1);
            }
        }
        __syncthreads();
    }

    const int r = row0 + wr * 16 + (lane >> 2);
#pragma unroll
    for (int t = 0; t < 4; t++) {
        int n = n0 + wcl * 32 + t * 8 + 2 * (lane & 3);
        float b0v = __ldg(&bias[n]), b1v = __ldg(&bias[n + 1]);
        float v00 = acc[t][0] + b0v, v01 = acc[t][1] + b1v;
        float v10 = acc[t][2] + b0v, v11 = acc[t][3] + b1v;
        if (RELU) {
            v00 = fmaxf(v00, 0.f); v01 = fmaxf(v01, 0.f);
            v10 = fmaxf(v10, 0.f); v11 = fmaxf(v11, 0.f);
        }
        C[(size_t)r * 512 + n]           = v00;
        C[(size_t)r * 512 + n + 1]       = v01;
        C[(size_t)(r + 8) * 512 + n]     = v10;
        C[(size_t)(r + 8) * 512 + n + 1] = v11;
    }
}

// ---------------- fused attention (tf32 mma, packed B, occ 2) --------------
__global__ __launch_bounds__(256, 2)
void attn_mma(const float* __restrict__ men, const float* __restrict__ vis,
              const unsigned* __restrict__ awp,
              const float* __restrict__ ab1, const float* __restrict__ aw2,
              const float* __restrict__ ab2,
              const float* __restrict__ mm, const float* __restrict__ cm,
              float* __restrict__ out)
{
    __shared__ __align__(16) float    men_s[2][32][36];
    __shared__ __align__(16) float    vis_s[2][4][36];
    __shared__ __align__(16) unsigned b_pk[2][4608];   // 8 chunks x 576 words
    __shared__ float attn_s[2][4][32];

    const int tid = threadIdx.x;
    const int lane = tid & 31, wid = tid >> 5;
    const int wc = wid >> 1;        // class within tile (0..3)
    const int wn = wid & 1;         // n-half (0..1) -> 64 cols
    const int c0 = blockIdx.x * 4;
    const int m0 = blockIdx.y * 32;
    const int b  = blockIdx.z;

    const float* menB = men + (size_t)(b * 64 + m0) * 512;
    const float* visB = vis + (size_t)(b * 36 + c0) * 512;

    float acc0[8][4], acc1[8][4];
    float attn_acc[4] = {0.f, 0.f, 0.f, 0.f};

    auto issue = [&](int s) {
        int buf = s & 1;
        int ksi = s & 15, ni = s >> 4;
        int k0 = ksi * 32;
        {   // men: 32 rows x 32 k
            int r = tid >> 3, k4 = tid & 7;
            cp16(&men_s[buf][r][k4 * 4], menB + (size_t)r * 512 + k0 + k4 * 4);
        }
        if (tid < 32) {  // vis: 4 x 32
            int c = tid >> 3, k4 = tid & 7;
            cp16(&vis_s[buf][c][k4 * 4], visB + (size_t)c * 512 + k0 + k4 * 4);
        }
        // packed aw1 stage block: 8 chunks x 576 words = 1152 x 16B, linear
        const unsigned* srcB = awp + (size_t)(ni * 16 + ksi) * 8 * 576;
#pragma unroll
        for (int p = 0; p < 5; p++) {
            int id = tid + p * 256;
            if (id < 1152) cp16(&b_pk[buf][id * 4], srcB + id * 4);
        }
    };

    issue(0);
    CP_COMMIT();

    for (int s = 0; s < 64; s++) {
        if (s + 1 < 64) { issue(s + 1); CP_COMMIT(); CP_WAIT1(); }
        else            { CP_WAIT0(); }
        __syncthreads();

        const int buf = s & 1;
        const int ks = s & 15, ni = s >> 4;

        if (ks == 0) {
#pragma unroll
            for (int t = 0; t < 8; t++)
#pragma unroll
                for (int j = 0; j < 4; j++) { acc0[t][j] = 0.f; acc1[t][j] = 0.f; }
        }

#pragma unroll
        for (int kc = 0; kc < 4; kc++) {
            const int k0 = kc * 8;
            const int kA = k0 + (lane & 3);
            const int mr = lane >> 2;
            float v0 = vis_s[buf][wc][kA];
            float v1 = vis_s[buf][wc][kA + 4];
            float m00 = men_s[buf][mr][kA],      m01 = men_s[buf][mr][kA + 4];
            float m10 = men_s[buf][mr + 8][kA],  m11 = men_s[buf][mr + 8][kA + 4];
            float m20 = men_s[buf][mr + 16][kA], m21 = men_s[buf][mr + 16][kA + 4];
            float m30 = men_s[buf][mr + 24][kA], m31 = men_s[buf][mr + 24][kA + 4];
            unsigned a00 = f2tf32(m00 * v0), a01 = f2tf32(m10 * v0);
            unsigned a02 = f2tf32(m01 * v1), a03 = f2tf32(m11 * v1);
            unsigned a10 = f2tf32(m20 * v0), a11 = f2tf32(m30 * v0);
            unsigned a12 = f2tf32(m21 * v1), a13 = f2tf32(m31 * v1);

            // B fragments: 4x LDS.128 from packed chunk (conflict-free skew)
            const int cbase = (kc * 2 + wn) * 576 + lane * 16 + (lane >> 1) * 4;
            uint4 q0 = *(const uint4*)&b_pk[buf][cbase];
            uint4 q1 = *(const uint4*)&b_pk[buf][cbase + 4];
            uint4 q2 = *(const uint4*)&b_pk[buf][cbase + 8];
            uint4 q3 = *(const uint4*)&b_pk[buf][cbase + 12];
            unsigned bq[16] = {q0.x, q0.y, q0.z, q0.w, q1.x, q1.y, q1.z, q1.w,
                               q2.x, q2.y, q2.z, q2.w, q3.x, q3.y, q3.z, q3.w};
#pragma unroll
            for (int t = 0; t < 8; t++) {
                mma_tf32(acc0[t], a00, a01, a02, a03, bq[t * 2], bq[t * 2 + 1]);
                mma_tf32(acc1[t], a10, a11, a12, a13, bq[t * 2], bq[t * 2 + 1]);
            }
        }

        if (ks == 15) {
            const int nbase = ni * 128 + wn * 64;
#pragma unroll
            for (int t = 0; t < 8; t++) {
                int n = nbase + t * 8 + 2 * (lane & 3);
                float bb0 = __ldg(&ab1[n]),     bb1 = __ldg(&ab1[n + 1]);
                float w0  = __ldg(&aw2[n]),     w1  = __ldg(&aw2[n + 1]);
                attn_acc[0] += fmaxf(acc0[t][0] + bb0, 0.f) * w0
                             + fmaxf(acc0[t][1] + bb1, 0.f) * w1;
                attn_acc[1] += fmaxf(acc0[t][2] + bb0, 0.f) * w0
                             + fmaxf(acc0[t][3] + bb1, 0.f) * w1;
                attn_acc[2] += fmaxf(acc1[t][0] + bb0, 0.f) * w0
                             + fmaxf(acc1[t][1] + bb1, 0.f) * w1;
                attn_acc[3] += fmaxf(acc1[t][2] + bb0, 0.f) * w0
                             + fmaxf(acc1[t][3] + bb1, 0.f) * w1;
            }
        }
        __syncthreads();
    }

#pragma unroll
    for (int i = 0; i < 4; i++) {
        float v = attn_acc[i];
        v += __shfl_xor_sync(0xffffffffu, v, 1);
        v += __shfl_xor_sync(0xffffffffu, v, 2);
        if ((lane & 3) == 0) attn_s[wn][wc][i * 8 + (lane >> 2)] = v;
    }
    __syncthreads();

    if (tid < 128) {
        int m = tid & 31, c = tid >> 5;
        float v = attn_s[0][c][m] + attn_s[1][c][m] + ab2[0];
        int gm = m0 + m, gc = c0 + c;
        v *= mm[b * 64 + gm] * cm[b * 36 + gc];
        out[(size_t)(b * 64 + gm) * 36 + gc] = (v != 0.f) ? v : NEG_INF_F;
    }
}

// ---------------- launch ---------------------------------------------------
extern "C" void kernel_launch(void* const* d_in, const int* in_sizes, int n_in,
                              void* d_out, int out_size)
{
    const float* me  = (const float*)d_in[0];
    const float* cl  = (const float*)d_in[1];
    const float* mm  = (const float*)d_in[2];
    const float* cm  = (const float*)d_in[3];
    const float* vw1 = (const float*)d_in[4];
    const float* vb1 = (const float*)d_in[5];
    const float* vw2 = (const float*)d_in[6];
    const float* vb2 = (const float*)d_in[7];
    const float* mw1 = (const float*)d_in[8];
    const float* mb1 = (const float*)d_in[9];
    const float* mw2 = (const float*)d_in[10];
    const float* mb2 = (const float*)d_in[11];
    const float* aw1 = (const float*)d_in[12];
    const float* ab1 = (const float*)d_in[13];
    const float* aw2 = (const float*)d_in[14];
    const float* ab2 = (const float*)d_in[15];
    float* out = (float*)d_out;

    void *p;
    cudaGetSymbolAddress(&p, g_men_h);  float*    men_h = (float*)p;
    cudaGetSymbolAddress(&p, g_men);    float*    menp  = (float*)p;
    cudaGetSymbolAddress(&p, g_vis_h);  float*    vis_h = (float*)p;
    cudaGetSymbolAddress(&p, g_vis);    float*    visp  = (float*)p;
    cudaGetSymbolAddress(&p, g_cl_pad); float*    clp   = (float*)p;
    cudaGetSymbolAddress(&p, g_mw1t);   unsigned* mw1t  = (unsigned*)p;
    cudaGetSymbolAddress(&p, g_mw2t);   unsigned* mw2t  = (unsigned*)p;
    cudaGetSymbolAddress(&p, g_vw1t);   unsigned* vw1t  = (unsigned*)p;
    cudaGetSymbolAddress(&p, g_vw2t);   unsigned* vw2t  = (unsigned*)p;
    cudaGetSymbolAddress(&p, g_aw1p);   unsigned* awp   = (unsigned*)p;

    // all prep in one launch (launch #0)
    prep_all<<<4736, 256>>>(cl, clp, mw1, mw1t, mw2, mw2t,
                            vw1, vw1t, vw2, vw2t, aw1, awp);

    // MLPs (launches #1..#4)
    gemm_mma<true ><<<dim3(8, 32), 256>>>(me,    mw1t, mb1, men_h, 1024);
    gemm_mma<false><<<dim3(8, 32), 256>>>(men_h, mw2t, mb2, menp,   512);
    gemm_mma<true ><<<dim3(8, 18), 256>>>(clp,   vw1t, vb1, vis_h, 1024);
    gemm_mma<false><<<dim3(8, 18), 256>>>(vis_h, vw2t, vb2, visp,   512);

    // fused attention (launch #5 — lands on ncu's -s 5 -c 1 window)
    attn_mma<<<dim3(9, 2, 32), 256>>>(menp, visp, awp, ab1, aw2, ab2,
                                      mm, cm, out);
}

// round 5
// speedup vs baseline: 7.8453x; 1.0610x over previous
#include <cuda_runtime.h>

#define NEG_INF_F (-1e10f)
// Shapes: B=32, M=64, C=36, INPUT=1024, HID=512, NCLASS=1000 (padded to 1024)

// ---------------- scratch (device globals; no allocation allowed) ----------
__device__ float    g_men_h[2048 * 512];
__device__ float    g_men  [2048 * 512];
__device__ float    g_vis_h[1152 * 512];
__device__ float    g_vis  [1152 * 512];
__device__ float    g_cl_pad[1152 * 1024];
__device__ unsigned g_mw1t[1024 * 512];
__device__ unsigned g_mw2t[ 512 * 512];
__device__ unsigned g_vw1t[1024 * 512];
__device__ unsigned g_vw2t[ 512 * 512];
// aw1 packed in mma-fragment order: 512 chunks x 576 words (incl. skew holes)
__device__ __align__(16) unsigned g_aw1p[512 * 576];

// ---------------- PTX helpers ---------------------------------------------
__device__ __forceinline__ unsigned f2tf32(float x) {
    unsigned u;
    asm("cvt.rna.tf32.f32 %0, %1;" : "=r"(u) : "f"(x));
    return u;
}

__device__ __forceinline__ void mma_tf32(float c[4],
                                         unsigned a0, unsigned a1, unsigned a2, unsigned a3,
                                         unsigned b0, unsigned b1) {
    asm volatile(
        "mma.sync.aligned.m16n8k8.row.col.f32.tf32.tf32.f32 "
        "{%0,%1,%2,%3}, {%4,%5,%6,%7}, {%8,%9}, {%0,%1,%2,%3};\n"
        : "+f"(c[0]), "+f"(c[1]), "+f"(c[2]), "+f"(c[3])
        : "r"(a0), "r"(a1), "r"(a2), "r"(a3), "r"(b0), "r"(b1));
}

__device__ __forceinline__ void cp16(void* smem, const void* gmem) {
    unsigned s = (unsigned)__cvta_generic_to_shared(smem);
    asm volatile("cp.async.cg.shared.global [%0], [%1], 16;\n" :: "r"(s), "l"(gmem));
}
#define CP_COMMIT() asm volatile("cp.async.commit_group;\n" ::: "memory")
#define CP_WAIT0()  asm volatile("cp.async.wait_group 0;\n" ::: "memory")
#define CP_WAIT1()  asm volatile("cp.async.wait_group 1;\n" ::: "memory")

// ---------------- single merged prep kernel --------------------------------
__global__ __launch_bounds__(256)
void prep_all(const float* __restrict__ cl,  float* __restrict__ clp,
              const float* __restrict__ mw1, unsigned* __restrict__ mw1t,
              const float* __restrict__ mw2, unsigned* __restrict__ mw2t,
              const float* __restrict__ vw1, unsigned* __restrict__ vw1t,
              const float* __restrict__ vw2, unsigned* __restrict__ vw2t,
              const float* __restrict__ aw1, unsigned* __restrict__ awp)
{
    const int b = blockIdx.x, t = threadIdx.x;
    if (b < 1152) {
        for (int c = t; c < 1024; c += 256)
            clp[b * 1024 + c] = (c < 1000) ? cl[b * 1000 + c] : 0.f;
    } else if (b < 2176) {
        int r = b - 1152;
        for (int c = t; c < 512; c += 256) mw1t[r * 512 + c] = f2tf32(mw1[r * 512 + c]);
    } else if (b < 2688) {
        int r = b - 2176;
        for (int c = t; c < 512; c += 256) mw2t[r * 512 + c] = f2tf32(mw2[r * 512 + c]);
    } else if (b < 3712) {
        int r = b - 2688;
        for (int c = t; c < 512; c += 256)
            vw1t[r * 512 + c] = (r < 1000) ? f2tf32(vw1[r * 512 + c]) : 0u;
    } else if (b < 4224) {
        int r = b - 3712;
        for (int c = t; c < 512; c += 256) vw2t[r * 512 + c] = f2tf32(vw2[r * 512 + c]);
    } else {
        // pack aw1 into fragment-order chunks (see attn_mma)
        int chunk = b - 4224;
        int h   = chunk & 1;
        int kc  = (chunk >> 1) & 3;
        int ksi = (chunk >> 3) & 15;
        int ni  = chunk >> 7;
#pragma unroll
        for (int p = 0; p < 2; p++) {
            int idx = t + p * 256;
            int l = idx >> 4, v = idx & 15;
            int k = ksi * 32 + kc * 8 + (l & 3) + 4 * (v & 1);
            int n = ni * 128 + h * 64 + (v >> 1) * 8 + (l >> 2);
            awp[chunk * 576 + l * 16 + (l >> 1) * 4 + v] = f2tf32(aw1[k * 512 + n]);
        }
    }
}

// ---------------- merged MLP GEMM (two row segments, one launch) -----------
// Segment 0 (blockIdx.y < y_split): C0 = act(A0 @ W0 + b0)  [2048 rows]
// Segment 1 (else):                 C1 = act(A1 @ W1 + b1)  [1152 rows]
// N = 512, same K for both segments. Per-block math identical to round 3/4.
template <bool RELU>
__global__ __launch_bounds__(256)
void gemm_mma2(const float* __restrict__ A0, const unsigned* __restrict__ W0,
               const float* __restrict__ b0p, float* __restrict__ C0,
               const float* __restrict__ A1, const unsigned* __restrict__ W1,
               const float* __restrict__ b1p, float* __restrict__ C1,
               int K, int y_split)
{
    __shared__ __align__(16) float    A_s[2][64][36];
    __shared__ __align__(16) unsigned B_s[2][32][72];

    const int tid = threadIdx.x;
    const int lane = tid & 31, wid = tid >> 5;
    const int wr = wid >> 1;
    const int wcl = wid & 1;

    const bool seg1 = (int)blockIdx.y >= y_split;
    const float*    A    = seg1 ? A1 : A0;
    const unsigned* W    = seg1 ? W1 : W0;
    const float*    bias = seg1 ? b1p : b0p;
    float*          C    = seg1 ? C1 : C0;
    const int row0 = (seg1 ? (blockIdx.y - y_split) : blockIdx.y) * 64;
    const int n0   = blockIdx.x * 64;

    float acc[4][4];
#pragma unroll
    for (int t = 0; t < 4; t++)
#pragma unroll
        for (int j = 0; j < 4; j++) acc[t][j] = 0.f;

    const int S = K >> 5;

    auto issue = [&](int s) {
        int buf = s & 1, k0 = s << 5;
#pragma unroll
        for (int p = 0; p < 2; p++) {
            int id = tid + p * 256;
            int r = id >> 3, k4 = id & 7;
            cp16(&A_s[buf][r][k4 * 4], A + (size_t)(row0 + r) * K + k0 + k4 * 4);
        }
#pragma unroll
        for (int p = 0; p < 2; p++) {
            int id = tid + p * 256;
            int kk = id >> 4, n4 = id & 15;
            cp16(&B_s[buf][kk][n4 * 4], W + (size_t)(k0 + kk) * 512 + n0 + n4 * 4);
        }
    };

    issue(0);
    CP_COMMIT();

    for (int s = 0; s < S; s++) {
        if (s + 1 < S) { issue(s + 1); CP_COMMIT(); CP_WAIT1(); }
        else           { CP_WAIT0(); }
        __syncthreads();
        const int buf = s & 1;
#pragma unroll
        for (int kc = 0; kc < 4; kc++) {
            const int k0 = kc * 8;
            const int ar = wr * 16 + (lane >> 2);
            const int ak = k0 + (lane & 3);
            unsigned a0 = f2tf32(A_s[buf][ar][ak]);
            unsigned a1 = f2tf32(A_s[buf][ar + 8][ak]);
            unsigned a2 = f2tf32(A_s[buf][ar][ak + 4]);
            unsigned a3 = f2tf32(A_s[buf][ar + 8][ak + 4]);
            const int bn = wcl * 32 + (lane >> 2);
#pragma unroll
            for (int t = 0; t < 4; t++) {
                unsigned b0 = B_s[buf][k0 + (lane & 3)][bn + t * 8];
                unsigned b1 = B_s[buf][k0 + (lane & 3) + 4][bn + t * 8];
                mma_tf32(acc[t], a0, a1, a2, a3, b0, b1);
            }
        }
        __syncthreads();
    }

    const int r = row0 + wr * 16 + (lane >> 2);
#pragma unroll
    for (int t = 0; t < 4; t++) {
        int n = n0 + wcl * 32 + t * 8 + 2 * (lane & 3);
        float b0v = __ldg(&bias[n]), b1v = __ldg(&bias[n + 1]);
        float v00 = acc[t][0] + b0v, v01 = acc[t][1] + b1v;
        float v10 = acc[t][2] + b0v, v11 = acc[t][3] + b1v;
        if (RELU) {
            v00 = fmaxf(v00, 0.f); v01 = fmaxf(v01, 0.f);
            v10 = fmaxf(v10, 0.f); v11 = fmaxf(v11, 0.f);
        }
        C[(size_t)r * 512 + n]           = v00;
        C[(size_t)r * 512 + n + 1]       = v01;
        C[(size_t)(r + 8) * 512 + n]     = v10;
        C[(size_t)(r + 8) * 512 + n + 1] = v11;
    }
}

// ---------------- fused attention (tf32 mma, packed B, occ 2) --------------
// (unchanged from round 4 — proven correct at 6.05e-4)
__global__ __launch_bounds__(256, 2)
void attn_mma(const float* __restrict__ men, const float* __restrict__ vis,
              const unsigned* __restrict__ awp,
              const float* __restrict__ ab1, const float* __restrict__ aw2,
              const float* __restrict__ ab2,
              const float* __restrict__ mm, const float* __restrict__ cm,
              float* __restrict__ out)
{
    __shared__ __align__(16) float    men_s[2][32][36];
    __shared__ __align__(16) float    vis_s[2][4][36];
    __shared__ __align__(16) unsigned b_pk[2][4608];
    __shared__ float attn_s[2][4][32];

    const int tid = threadIdx.x;
    const int lane = tid & 31, wid = tid >> 5;
    const int wc = wid >> 1;
    const int wn = wid & 1;
    const int c0 = blockIdx.x * 4;
    const int m0 = blockIdx.y * 32;
    const int b  = blockIdx.z;

    const float* menB = men + (size_t)(b * 64 + m0) * 512;
    const float* visB = vis + (size_t)(b * 36 + c0) * 512;

    float acc0[8][4], acc1[8][4];
    float attn_acc[4] = {0.f, 0.f, 0.f, 0.f};

    auto issue = [&](int s) {
        int buf = s & 1;
        int ksi = s & 15, ni = s >> 4;
        int k0 = ksi * 32;
        {
            int r = tid >> 3, k4 = tid & 7;
            cp16(&men_s[buf][r][k4 * 4], menB + (size_t)r * 512 + k0 + k4 * 4);
        }
        if (tid < 32) {
            int c = tid >> 3, k4 = tid & 7;
            cp16(&vis_s[buf][c][k4 * 4], visB + (size_t)c * 512 + k0 + k4 * 4);
        }
        const unsigned* srcB = awp + (size_t)(ni * 16 + ksi) * 8 * 576;
#pragma unroll
        for (int p = 0; p < 5; p++) {
            int id = tid + p * 256;
            if (id < 1152) cp16(&b_pk[buf][id * 4], srcB + id * 4);
        }
    };

    issue(0);
    CP_COMMIT();

    for (int s = 0; s < 64; s++) {
        if (s + 1 < 64) { issue(s + 1); CP_COMMIT(); CP_WAIT1(); }
        else            { CP_WAIT0(); }
        __syncthreads();

        const int buf = s & 1;
        const int ks = s & 15, ni = s >> 4;

        if (ks == 0) {
#pragma unroll
            for (int t = 0; t < 8; t++)
#pragma unroll
                for (int j = 0; j < 4; j++) { acc0[t][j] = 0.f; acc1[t][j] = 0.f; }
        }

#pragma unroll
        for (int kc = 0; kc < 4; kc++) {
            const int k0 = kc * 8;
            const int kA = k0 + (lane & 3);
            const int mr = lane >> 2;
            float v0 = vis_s[buf][wc][kA];
            float v1 = vis_s[buf][wc][kA + 4];
            float m00 = men_s[buf][mr][kA],      m01 = men_s[buf][mr][kA + 4];
            float m10 = men_s[buf][mr + 8][kA],  m11 = men_s[buf][mr + 8][kA + 4];
            float m20 = men_s[buf][mr + 16][kA], m21 = men_s[buf][mr + 16][kA + 4];
            float m30 = men_s[buf][mr + 24][kA], m31 = men_s[buf][mr + 24][kA + 4];
            unsigned a00 = f2tf32(m00 * v0), a01 = f2tf32(m10 * v0);
            unsigned a02 = f2tf32(m01 * v1), a03 = f2tf32(m11 * v1);
            unsigned a10 = f2tf32(m20 * v0), a11 = f2tf32(m30 * v0);
            unsigned a12 = f2tf32(m21 * v1), a13 = f2tf32(m31 * v1);

            const int cbase = (kc * 2 + wn) * 576 + lane * 16 + (lane >> 1) * 4;
            uint4 q0 = *(const uint4*)&b_pk[buf][cbase];
            uint4 q1 = *(const uint4*)&b_pk[buf][cbase + 4];
            uint4 q2 = *(const uint4*)&b_pk[buf][cbase + 8];
            uint4 q3 = *(const uint4*)&b_pk[buf][cbase + 12];
            unsigned bq[16] = {q0.x, q0.y, q0.z, q0.w, q1.x, q1.y, q1.z, q1.w,
                               q2.x, q2.y, q2.z, q2.w, q3.x, q3.y, q3.z, q3.w};
#pragma unroll
            for (int t = 0; t < 8; t++) {
                mma_tf32(acc0[t], a00, a01, a02, a03, bq[t * 2], bq[t * 2 + 1]);
                mma_tf32(acc1[t], a10, a11, a12, a13, bq[t * 2], bq[t * 2 + 1]);
            }
        }

        if (ks == 15) {
            const int nbase = ni * 128 + wn * 64;
#pragma unroll
            for (int t = 0; t < 8; t++) {
                int n = nbase + t * 8 + 2 * (lane & 3);
                float bb0 = __ldg(&ab1[n]),     bb1 = __ldg(&ab1[n + 1]);
                float w0  = __ldg(&aw2[n]),     w1  = __ldg(&aw2[n + 1]);
                attn_acc[0] += fmaxf(acc0[t][0] + bb0, 0.f) * w0
                             + fmaxf(acc0[t][1] + bb1, 0.f) * w1;
                attn_acc[1] += fmaxf(acc0[t][2] + bb0, 0.f) * w0
                             + fmaxf(acc0[t][3] + bb1, 0.f) * w1;
                attn_acc[2] += fmaxf(acc1[t][0] + bb0, 0.f) * w0
                             + fmaxf(acc1[t][1] + bb1, 0.f) * w1;
                attn_acc[3] += fmaxf(acc1[t][2] + bb0, 0.f) * w0
                             + fmaxf(acc1[t][3] + bb1, 0.f) * w1;
            }
        }
        __syncthreads();
    }

#pragma unroll
    for (int i = 0; i < 4; i++) {
        float v = attn_acc[i];
        v += __shfl_xor_sync(0xffffffffu, v, 1);
        v += __shfl_xor_sync(0xffffffffu, v, 2);
        if ((lane & 3) == 0) attn_s[wn][wc][i * 8 + (lane >> 2)] = v;
    }
    __syncthreads();

    if (tid < 128) {
        int m = tid & 31, c = tid >> 5;
        float v = attn_s[0][c][m] + attn_s[1][c][m] + ab2[0];
        int gm = m0 + m, gc = c0 + c;
        v *= mm[b * 64 + gm] * cm[b * 36 + gc];
        out[(size_t)(b * 64 + gm) * 36 + gc] = (v != 0.f) ? v : NEG_INF_F;
    }
}

// ---------------- launch ---------------------------------------------------
extern "C" void kernel_launch(void* const* d_in, const int* in_sizes, int n_in,
                              void* d_out, int out_size)
{
    const float* me  = (const float*)d_in[0];
    const float* cl  = (const float*)d_in[1];
    const float* mm  = (const float*)d_in[2];
    const float* cm  = (const float*)d_in[3];
    const float* vw1 = (const float*)d_in[4];
    const float* vb1 = (const float*)d_in[5];
    const float* vw2 = (const float*)d_in[6];
    const float* vb2 = (const float*)d_in[7];
    const float* mw1 = (const float*)d_in[8];
    const float* mb1 = (const float*)d_in[9];
    const float* mw2 = (const float*)d_in[10];
    const float* mb2 = (const float*)d_in[11];
    const float* aw1 = (const float*)d_in[12];
    const float* ab1 = (const float*)d_in[13];
    const float* aw2 = (const float*)d_in[14];
    const float* ab2 = (const float*)d_in[15];
    float* out = (float*)d_out;

    void *p;
    cudaGetSymbolAddress(&p, g_men_h);  float*    men_h = (float*)p;
    cudaGetSymbolAddress(&p, g_men);    float*    menp  = (float*)p;
    cudaGetSymbolAddress(&p, g_vis_h);  float*    vis_h = (float*)p;
    cudaGetSymbolAddress(&p, g_vis);    float*    visp  = (float*)p;
    cudaGetSymbolAddress(&p, g_cl_pad); float*    clp   = (float*)p;
    cudaGetSymbolAddress(&p, g_mw1t);   unsigned* mw1t  = (unsigned*)p;
    cudaGetSymbolAddress(&p, g_mw2t);   unsigned* mw2t  = (unsigned*)p;
    cudaGetSymbolAddress(&p, g_vw1t);   unsigned* vw1t  = (unsigned*)p;
    cudaGetSymbolAddress(&p, g_vw2t);   unsigned* vw2t  = (unsigned*)p;
    cudaGetSymbolAddress(&p, g_aw1p);   unsigned* awp   = (unsigned*)p;

    // #0: all prep
    prep_all<<<4736, 256>>>(cl, clp, mw1, mw1t, mw2, mw2t,
                            vw1, vw1t, vw2, vw2t, aw1, awp);

    // #1: layer-1 of both MLPs (K=1024), 400 blocks -> 2-3 resident/SM
    gemm_mma2<true ><<<dim3(8, 50), 256>>>(me,    mw1t, mb1, men_h,
                                           clp,   vw1t, vb1, vis_h, 1024, 32);
    // #2: layer-2 of both MLPs (K=512)
    gemm_mma2<false><<<dim3(8, 50), 256>>>(men_h, mw2t, mb2, menp,
                                           vis_h, vw2t, vb2, visp,  512, 32);

    // #3: fused attention (lands on ncu's skip window -> profiled next round)
    attn_mma<<<dim3(9, 2, 32), 256>>>(menp, visp, awp, ab1, aw2, ab2,
                                      mm, cm, out);
}

// round 12
// speedup vs baseline: 7.8577x; 1.0016x over previous
#include <cuda_runtime.h>
#include <cstdint>

#define NEG_INF_F (-1e10f)
// Shapes: B=32, M=64, C=36, INPUT=1024, HID=512, NCLASS=1000 (padded to 1024)

// ---------------- scratch (device globals; no allocation allowed) ----------
__device__ float    g_men_h[2048 * 512];
__device__ float    g_men  [2048 * 512];
__device__ float    g_vis_h[1152 * 512];
__device__ float    g_vis  [1152 * 512];
__device__ float    g_cl_pad[1152 * 1024];
__device__ unsigned g_mw1t[1024 * 512];
__device__ unsigned g_mw2t[ 512 * 512];
__device__ unsigned g_vw1t[1024 * 512];
__device__ unsigned g_vw2t[ 512 * 512];
// aw1 packed in mma-fragment order: 512 chunks x 576 words (incl. skew holes)
__device__ __align__(16) unsigned g_aw1p[512 * 576];

// ---------------- PTX helpers ---------------------------------------------
__device__ __forceinline__ unsigned f2tf32(float x) {
    unsigned u;
    asm("cvt.rna.tf32.f32 %0, %1;" : "=r"(u) : "f"(x));
    return u;
}

__device__ __forceinline__ void mma_tf32(float c[4],
                                         unsigned a0, unsigned a1, unsigned a2, unsigned a3,
                                         unsigned b0, unsigned b1) {
    asm volatile(
        "mma.sync.aligned.m16n8k8.row.col.f32.tf32.tf32.f32 "
        "{%0,%1,%2,%3}, {%4,%5,%6,%7}, {%8,%9}, {%0,%1,%2,%3};\n"
        : "+f"(c[0]), "+f"(c[1]), "+f"(c[2]), "+f"(c[3])
        : "r"(a0), "r"(a1), "r"(a2), "r"(a3), "r"(b0), "r"(b1));
}

__device__ __forceinline__ void cp16(void* smem, const void* gmem) {
    unsigned s = (unsigned)__cvta_generic_to_shared(smem);
    asm volatile("cp.async.cg.shared.global [%0], [%1], 16;\n" :: "r"(s), "l"(gmem));
}
__device__ __forceinline__ void cp16s(uint32_t smem_u32, const void* gmem) {
    asm volatile("cp.async.cg.shared.global [%0], [%1], 16;\n" :: "r"(smem_u32), "l"(gmem));
}
#define CP_COMMIT() asm volatile("cp.async.commit_group;\n" ::: "memory")
#define CP_WAIT0()  asm volatile("cp.async.wait_group 0;\n" ::: "memory")
#define CP_WAIT1()  asm volatile("cp.async.wait_group 1;\n" ::: "memory")

// ---------------- merged prep kernel ---------------------------------------
//  [0,1152)     pad class_labels 1000 -> 1024
//  [1152,2176)  cvt mw1   [2176,2688) cvt mw2
//  [2688,3712)  cvt vw1 (zero-pad rows >=1000)   [3712,4224) cvt vw2
//  [4224,4736)  pack aw1 into fragment-order chunks
__global__ __launch_bounds__(256)
void prep_all(const float* __restrict__ cl,  float* __restrict__ clp,
              const float* __restrict__ mw1, unsigned* __restrict__ mw1t,
              const float* __restrict__ mw2, unsigned* __restrict__ mw2t,
              const float* __restrict__ vw1, unsigned* __restrict__ vw1t,
              const float* __restrict__ vw2, unsigned* __restrict__ vw2t,
              const float* __restrict__ aw1, unsigned* __restrict__ awp)
{
    const int b = blockIdx.x, t = threadIdx.x;
    if (b < 1152) {
        for (int c = t; c < 1024; c += 256)
            clp[b * 1024 + c] = (c < 1000) ? cl[b * 1000 + c] : 0.f;
    } else if (b < 2176) {
        int r = b - 1152;
        for (int c = t; c < 512; c += 256) mw1t[r * 512 + c] = f2tf32(mw1[r * 512 + c]);
    } else if (b < 2688) {
        int r = b - 2176;
        for (int c = t; c < 512; c += 256) mw2t[r * 512 + c] = f2tf32(mw2[r * 512 + c]);
    } else if (b < 3712) {
        int r = b - 2688;
        for (int c = t; c < 512; c += 256)
            vw1t[r * 512 + c] = (r < 1000) ? f2tf32(vw1[r * 512 + c]) : 0u;
    } else if (b < 4224) {
        int r = b - 3712;
        for (int c = t; c < 512; c += 256) vw2t[r * 512 + c] = f2tf32(vw2[r * 512 + c]);
    } else {
        // chunk = ((ni*16 + ksi)*4 + kc)*2 + h covers 8k x 64n.
        // Value (l, v): k = ksi*32+kc*8+(l&3)+4*(v&1), n = ni*128+h*64+(v>>1)*8+(l>>2).
        // In-chunk word offset = l*16 + (l>>1)*4 + v  (skew -> conflict-free LDS.128)
        int chunk = b - 4224;
        int h   = chunk & 1;
        int kc  = (chunk >> 1) & 3;
        int ksi = (chunk >> 3) & 15;
        int ni  = chunk >> 7;
#pragma unroll
        for (int p = 0; p < 2; p++) {
            int idx = t + p * 256;
            int l = idx >> 4, v = idx & 15;
            int k = ksi * 32 + kc * 8 + (l & 3) + 4 * (v & 1);
            int n = ni * 128 + h * 64 + (v >> 1) * 8 + (l >> 2);
            awp[chunk * 576 + l * 16 + (l >> 1) * 4 + v] = f2tf32(aw1[k * 512 + n]);
        }
    }
}

// ---------------- merged MLP GEMM (two row segments, one launch) -----------
template <bool RELU>
__global__ __launch_bounds__(256)
void gemm_mma2(const float* __restrict__ A0, const unsigned* __restrict__ W0,
               const float* __restrict__ b0p, float* __restrict__ C0,
               const float* __restrict__ A1, const unsigned* __restrict__ W1,
               const float* __restrict__ b1p, float* __restrict__ C1,
               int K, int y_split)
{
    __shared__ __align__(16) float    A_s[2][64][36];
    __shared__ __align__(16) unsigned B_s[2][32][72];

    const int tid = threadIdx.x;
    const int lane = tid & 31, wid = tid >> 5;
    const int wr = wid >> 1, wcl = wid & 1;

    const bool seg1 = (int)blockIdx.y >= y_split;
    const float*    A    = seg1 ? A1 : A0;
    const unsigned* W    = seg1 ? W1 : W0;
    const float*    bias = seg1 ? b1p : b0p;
    float*          C    = seg1 ? C1 : C0;
    const int row0 = (seg1 ? (blockIdx.y - y_split) : blockIdx.y) * 64;
    const int n0   = blockIdx.x * 64;

    float acc[4][4];
#pragma unroll
    for (int t = 0; t < 4; t++)
#pragma unroll
        for (int j = 0; j < 4; j++) acc[t][j] = 0.f;

    const int S = K >> 5;
    auto issue = [&](int s) {
        int buf = s & 1, k0 = s << 5;
#pragma unroll
        for (int p = 0; p < 2; p++) {
            int id = tid + p * 256;
            int r = id >> 3, k4 = id & 7;
            cp16(&A_s[buf][r][k4 * 4], A + (size_t)(row0 + r) * K + k0 + k4 * 4);
        }
#pragma unroll
        for (int p = 0; p < 2; p++) {
            int id = tid + p * 256;
            int kk = id >> 4, n4 = id & 15;
            cp16(&B_s[buf][kk][n4 * 4], W + (size_t)(k0 + kk) * 512 + n0 + n4 * 4);
        }
    };

    issue(0);
    CP_COMMIT();

    for (int s = 0; s < S; s++) {
        if (s + 1 < S) { issue(s + 1); CP_COMMIT(); CP_WAIT1(); }
        else           { CP_WAIT0(); }
        __syncthreads();
        const int buf = s & 1;
#pragma unroll
        for (int kc = 0; kc < 4; kc++) {
            const int k0 = kc * 8;
            const int ar = wr * 16 + (lane >> 2);
            const int ak = k0 + (lane & 3);
            unsigned a0 = f2tf32(A_s[buf][ar][ak]);
            unsigned a1 = f2tf32(A_s[buf][ar + 8][ak]);
            unsigned a2 = f2tf32(A_s[buf][ar][ak + 4]);
            unsigned a3 = f2tf32(A_s[buf][ar + 8][ak + 4]);
            const int bn = wcl * 32 + (lane >> 2);
#pragma unroll
            for (int t = 0; t < 4; t++) {
                unsigned b0 = B_s[buf][k0 + (lane & 3)][bn + t * 8];
                unsigned b1 = B_s[buf][k0 + (lane & 3) + 4][bn + t * 8];
                mma_tf32(acc[t], a0, a1, a2, a3, b0, b1);
            }
        }
        __syncthreads();
    }

    const int r = row0 + wr * 16 + (lane >> 2);
#pragma unroll
    for (int t = 0; t < 4; t++) {
        int n = n0 + wcl * 32 + t * 8 + 2 * (lane & 3);
        float b0v = __ldg(&bias[n]), b1v = __ldg(&bias[n + 1]);
        float v00 = acc[t][0] + b0v, v01 = acc[t][1] + b1v;
        float v10 = acc[t][2] + b0v, v11 = acc[t][3] + b1v;
        if (RELU) {
            v00 = fmaxf(v00, 0.f); v01 = fmaxf(v01, 0.f);
            v10 = fmaxf(v10, 0.f); v11 = fmaxf(v11, 0.f);
        }
        C[(size_t)r * 512 + n]           = v00;
        C[(size_t)r * 512 + n + 1]       = v01;
        C[(size_t)(r + 8) * 512 + n]     = v10;
        C[(size_t)(r + 8) * 512 + n + 1] = v11;
    }
}

// ---------------- fused attention (tf32 mma.sync, hoisted addressing) ------
// Identical arithmetic to the proven 262.6us version; only address
// computation is hoisted/incremental and the bq[] register copy removed.
__global__ __launch_bounds__(256, 2)
void attn_mma(const float* __restrict__ men, const float* __restrict__ vis,
              const unsigned* __restrict__ awp,
              const float* __restrict__ ab1, const float* __restrict__ aw2,
              const float* __restrict__ ab2,
              const float* __restrict__ mm, const float* __restrict__ cm,
              float* __restrict__ out)
{
    __shared__ __align__(16) float    men_s[2][32][36];
    __shared__ __align__(16) float    vis_s[2][4][36];
    __shared__ __align__(16) unsigned b_pk[2][4608];   // 8 chunks x 576 words
    __shared__ float attn_s[2][4][32];

    const int tid = threadIdx.x;
    const int lane = tid & 31, wid = tid >> 5;
    const int wc = wid >> 1;        // class within tile (0..3)
    const int wn = wid & 1;         // n-half (0..1) -> 64 cols
    const int c0 = blockIdx.x * 4;
    const int m0 = blockIdx.y * 32;
    const int b  = blockIdx.z;

    const float* menB = men + (size_t)(b * 64 + m0) * 512;
    const float* visB = vis + (size_t)(b * 36 + c0) * 512;

    // ---- hoisted per-thread staging state (constant across stages) ----
    const int  r_m  = tid >> 3, k4_m = tid & 7;                 // men 32x32
    const float* men_src = menB + (size_t)r_m * 512 + k4_m * 4; // + (s&15)*32
    float* men_dst0 = &men_s[0][r_m][k4_m * 4];
    float* men_dst1 = &men_s[1][r_m][k4_m * 4];

    const int  c_v  = tid >> 3, k4_v = tid & 7;                 // vis 4x32 (tid<32)
    const float* vis_src = visB + (size_t)c_v * 512 + k4_v * 4;
    float* vis_dst0 = (tid < 32) ? &vis_s[0][c_v][k4_v * 4] : nullptr;
    float* vis_dst1 = (tid < 32) ? &vis_s[1][c_v][k4_v * 4] : nullptr;

    const unsigned* b_src = awp + (size_t)tid * 4;              // + s*4608
    const bool b_tail = (tid < 128);                            // id=tid+1024 < 1152

    // ---- hoisted compute-side constants ----
    const int laneoff = lane * 16 + (lane >> 1) * 4;            // skewed frag base
    const int mr = lane >> 2, kq = lane & 3;

    float acc0[8][4], acc1[8][4];
    float attn_acc[4] = {0.f, 0.f, 0.f, 0.f};

    auto issue = [&](int s) {
        const int buf = s & 1;
        const int koff = (s & 15) * 32;
        cp16(buf ? men_dst1 : men_dst0, men_src + koff);
        if (tid < 32) cp16(buf ? vis_dst1 : vis_dst0, vis_src + koff);
        const unsigned* src = b_src + (size_t)s * 4608;
        unsigned* dstb = &b_pk[buf][tid * 4];
#pragma unroll
        for (int p = 0; p < 4; p++)
            cp16(dstb + p * 1024, src + p * 1024);
        if (b_tail) cp16(dstb + 4096, src + 4096);
    };

    issue(0);
    CP_COMMIT();

    for (int s = 0; s < 64; s++) {
        if (s + 1 < 64) { issue(s + 1); CP_COMMIT(); CP_WAIT1(); }
        else            { CP_WAIT0(); }
        __syncthreads();

        const int buf = s & 1;
        const int ks = s & 15, ni = s >> 4;

        if (ks == 0) {
#pragma unroll
            for (int t = 0; t < 8; t++)
#pragma unroll
                for (int j = 0; j < 4; j++) { acc0[t][j] = 0.f; acc1[t][j] = 0.f; }
        }

#pragma unroll
        for (int kc = 0; kc < 4; kc++) {
            const int kA = kc * 8 + kq;
            float v0 = vis_s[buf][wc][kA];
            float v1 = vis_s[buf][wc][kA + 4];
            float m00 = men_s[buf][mr][kA],      m01 = men_s[buf][mr][kA + 4];
            float m10 = men_s[buf][mr + 8][kA],  m11 = men_s[buf][mr + 8][kA + 4];
            float m20 = men_s[buf][mr + 16][kA], m21 = men_s[buf][mr + 16][kA + 4];
            float m30 = men_s[buf][mr + 24][kA], m31 = men_s[buf][mr + 24][kA + 4];
            unsigned a00 = f2tf32(m00 * v0), a01 = f2tf32(m10 * v0);
            unsigned a02 = f2tf32(m01 * v1), a03 = f2tf32(m11 * v1);
            unsigned a10 = f2tf32(m20 * v0), a11 = f2tf32(m30 * v0);
            unsigned a12 = f2tf32(m21 * v1), a13 = f2tf32(m31 * v1);

            const unsigned* cb = &b_pk[buf][(kc * 2 + wn) * 576 + laneoff];
            uint4 q0 = *(const uint4*)(cb);
            uint4 q1 = *(const uint4*)(cb + 4);
            uint4 q2 = *(const uint4*)(cb + 8);
            uint4 q3 = *(const uint4*)(cb + 12);

            mma_tf32(acc0[0], a00, a01, a02, a03, q0.x, q0.y);
            mma_tf32(acc1[0], a10, a11, a12, a13, q0.x, q0.y);
            mma_tf32(acc0[1], a00, a01, a02, a03, q0.z, q0.w);
            mma_tf32(acc1[1], a10, a11, a12, a13, q0.z, q0.w);
            mma_tf32(acc0[2], a00, a01, a02, a03, q1.x, q1.y);
            mma_tf32(acc1[2], a10, a11, a12, a13, q1.x, q1.y);
            mma_tf32(acc0[3], a00, a01, a02, a03, q1.z, q1.w);
            mma_tf32(acc1[3], a10, a11, a12, a13, q1.z, q1.w);
            mma_tf32(acc0[4], a00, a01, a02, a03, q2.x, q2.y);
            mma_tf32(acc1[4], a10, a11, a12, a13, q2.x, q2.y);
            mma_tf32(acc0[5], a00, a01, a02, a03, q2.z, q2.w);
            mma_tf32(acc1[5], a10, a11, a12, a13, q2.z, q2.w);
            mma_tf32(acc0[6], a00, a01, a02, a03, q3.x, q3.y);
            mma_tf32(acc1[6], a10, a11, a12, a13, q3.x, q3.y);
            mma_tf32(acc0[7], a00, a01, a02, a03, q3.z, q3.w);
            mma_tf32(acc1[7], a10, a11, a12, a13, q3.z, q3.w);
        }

        if (ks == 15) {
            const int nbase = ni * 128 + wn * 64;
#pragma unroll
            for (int t = 0; t < 8; t++) {
                int n = nbase + t * 8 + 2 * (lane & 3);
                float bb0 = __ldg(&ab1[n]),     bb1 = __ldg(&ab1[n + 1]);
                float w0  = __ldg(&aw2[n]),     w1  = __ldg(&aw2[n + 1]);
                attn_acc[0] += fmaxf(acc0[t][0] + bb0, 0.f) * w0
                             + fmaxf(acc0[t][1] + bb1, 0.f) * w1;
                attn_acc[1] += fmaxf(acc0[t][2] + bb0, 0.f) * w0
                             + fmaxf(acc0[t][3] + bb1, 0.f) * w1;
                attn_acc[2] += fmaxf(acc1[t][0] + bb0, 0.f) * w0
                             + fmaxf(acc1[t][1] + bb1, 0.f) * w1;
                attn_acc[3] += fmaxf(acc1[t][2] + bb0, 0.f) * w0
                             + fmaxf(acc1[t][3] + bb1, 0.f) * w1;
            }
        }
        __syncthreads();
    }

    // reduce the 4 col-pair lanes, stash per n-half partials
#pragma unroll
    for (int i = 0; i < 4; i++) {
        float v = attn_acc[i];
        v += __shfl_xor_sync(0xffffffffu, v, 1);
        v += __shfl_xor_sync(0xffffffffu, v, 2);
        if ((lane & 3) == 0) attn_s[wn][wc][i * 8 + (lane >> 2)] = v;
    }
    __syncthreads();

    if (tid < 128) {
        int m = tid & 31, c = tid >> 5;
        float v = attn_s[0][c][m] + attn_s[1][c][m] + ab2[0];
        int gm = m0 + m, gc = c0 + c;
        v *= mm[b * 64 + gm] * cm[b * 36 + gc];
        out[(size_t)(b * 64 + gm) * 36 + gc] = (v != 0.f) ? v : NEG_INF_F;
    }
}

// ---------------- launch ---------------------------------------------------
extern "C" void kernel_launch(void* const* d_in, const int* in_sizes, int n_in,
                              void* d_out, int out_size)
{
    const float* me  = (const float*)d_in[0];
    const float* cl  = (const float*)d_in[1];
    const float* mm  = (const float*)d_in[2];
    const float* cm  = (const float*)d_in[3];
    const float* vw1 = (const float*)d_in[4];
    const float* vb1 = (const float*)d_in[5];
    const float* vw2 = (const float*)d_in[6];
    const float* vb2 = (const float*)d_in[7];
    const float* mw1 = (const float*)d_in[8];
    const float* mb1 = (const float*)d_in[9];
    const float* mw2 = (const float*)d_in[10];
    const float* mb2 = (const float*)d_in[11];
    const float* aw1 = (const float*)d_in[12];
    const float* ab1 = (const float*)d_in[13];
    const float* aw2 = (const float*)d_in[14];
    const float* ab2 = (const float*)d_in[15];
    float* out = (float*)d_out;

    void *p;
    cudaGetSymbolAddress(&p, g_men_h);  float*    men_h = (float*)p;
    cudaGetSymbolAddress(&p, g_men);    float*    menp  = (float*)p;
    cudaGetSymbolAddress(&p, g_vis_h);  float*    vis_h = (float*)p;
    cudaGetSymbolAddress(&p, g_vis);    float*    visp  = (float*)p;
    cudaGetSymbolAddress(&p, g_cl_pad); float*    clp   = (float*)p;
    cudaGetSymbolAddress(&p, g_mw1t);   unsigned* mw1t  = (unsigned*)p;
    cudaGetSymbolAddress(&p, g_mw2t);   unsigned* mw2t  = (unsigned*)p;
    cudaGetSymbolAddress(&p, g_vw1t);   unsigned* vw1t  = (unsigned*)p;
    cudaGetSymbolAddress(&p, g_vw2t);   unsigned* vw2t  = (unsigned*)p;
    cudaGetSymbolAddress(&p, g_aw1p);   unsigned* awp   = (unsigned*)p;

    // #0: all prep
    prep_all<<<4736, 256>>>(cl, clp, mw1, mw1t, mw2, mw2t,
                            vw1, vw1t, vw2, vw2t, aw1, awp);

    // #1/#2: both MLP layers merged (400 blocks each -> 2-3 resident/SM)
    gemm_mma2<true ><<<dim3(8, 50), 256>>>(me,    mw1t, mb1, men_h,
                                           clp,   vw1t, vb1, vis_h, 1024, 32);
    gemm_mma2<false><<<dim3(8, 50), 256>>>(men_h, mw2t, mb2, menp,
                                           vis_h, vw2t, vb2, visp,  512, 32);

    // #3: fused attention (mma.sync tf32 — tcgen05 blocked by harness PTX target)
    attn_mma<<<dim3(9, 2, 32), 256>>>(menp, visp, awp, ab1, aw2, ab2,
                                      mm, cm, out);
}